// round 1
// baseline (speedup 1.0000x reference)
#include <cuda_runtime.h>
#include <math.h>
#include <stdint.h>

#define T_LEN 4096
#define NSIG  4096          // 16 * 256 signals
#define TOPK  7

// -------- scratch (module-scope device memory; no runtime allocation) -------
__device__ float2 d_tw[T_LEN];                  // e^{-2*pi*i*j/4096}
__device__ float  d_xT[16 * 256 * 4096];        // transposed input (b,d,t)
__device__ int    d_pk [NSIG * TOPK];           // selected frequency index k
__device__ float  d_pre[NSIG * TOPK];           // coefficient real = 4*Re(X)/T
__device__ float  d_pim[NSIG * TOPK];           // coefficient imag = 4*Im(X)/T

// ---------------------------------------------------------------------------
// K0: twiddle table in double precision (exact-ish regardless of fast-math)
// ---------------------------------------------------------------------------
__global__ void k_twiddle() {
    int j = blockIdx.x * blockDim.x + threadIdx.x;
    if (j < T_LEN) {
        double a = -2.0 * 3.14159265358979323846 * (double)j / 4096.0;
        d_tw[j] = make_float2((float)cos(a), (float)sin(a));
    }
}

// ---------------------------------------------------------------------------
// KT: (16,4096,256) -> (16,256,4096) tiled transpose, fully coalesced
// ---------------------------------------------------------------------------
__global__ void __launch_bounds__(256) k_transpose(const float* __restrict__ x) {
    __shared__ float tile[32][33];
    int b  = blockIdx.z;
    int t0 = blockIdx.x * 32;
    int d0 = blockIdx.y * 32;
    #pragma unroll
    for (int r = threadIdx.y; r < 32; r += 8)
        tile[r][threadIdx.x] =
            x[((size_t)b * 4096 + t0 + r) * 256 + d0 + threadIdx.x];
    __syncthreads();
    #pragma unroll
    for (int r = threadIdx.y; r < 32; r += 8)
        d_xT[((size_t)b * 256 + d0 + r) * 4096 + t0 + threadIdx.x] =
            tile[threadIdx.x][r];
}

// ---------------------------------------------------------------------------
// K1: two real signals packed in one complex radix-4 DIF FFT + top-7 select
// ---------------------------------------------------------------------------
__device__ __forceinline__ int dr12(int p) {   // base-4 digit reversal, 12 bits
    unsigned r = __brev((unsigned)p) >> 20;    // full bit reversal
    return (int)(((r & 0x555u) << 1) | ((r & 0xAAAu) >> 1)); // swap bit pairs
}
__device__ __forceinline__ float2 cmul(float2 a, float2 b) {
    return make_float2(a.x * b.x - a.y * b.y, a.x * b.y + a.y * b.x);
}

__global__ void __launch_bounds__(256) k_fft() {
    extern __shared__ float2 s_buf[];
    float2* z   = s_buf;            // 4096 complex points (32 KB)
    float2* tw  = s_buf + 4096;     // 4096 twiddles (32 KB), reused after FFT
    float*  aux = (float*)tw;       // 8192 floats of reusable space

    int tid = threadIdx.x;
    int b   = blockIdx.x >> 7;          // 16 batches
    int d0  = (blockIdx.x & 127) << 1;  // pair of d channels

    const float* r0 = d_xT + ((size_t)b * 256 + d0) * 4096;
    const float* r1 = r0 + 4096;
    for (int i = tid; i < 4096; i += 256) {
        z[i]  = make_float2(r0[i], r1[i]);   // pack two real signals
        tw[i] = d_tw[i];
    }
    __syncthreads();

    // 6 radix-4 DIF stages (in-place, output in base-4 digit-reversed order)
    #pragma unroll
    for (int s = 0; s < 6; s++) {
        int lm = 10 - 2 * s;     // log2(m), m = L/4
        int m  = 1 << lm;
        for (int j = tid; j < 1024; j += 256) {
            int q    = j & (m - 1);
            int base = ((j >> lm) << (lm + 2)) + q;
            float2 x0 = z[base], x1 = z[base + m], x2 = z[base + 2*m], x3 = z[base + 3*m];
            float2 t0 = make_float2(x0.x + x2.x, x0.y + x2.y);
            float2 t2 = make_float2(x0.x - x2.x, x0.y - x2.y);
            float2 t1 = make_float2(x1.x + x3.x, x1.y + x3.y);
            float2 t3 = make_float2(x1.x - x3.x, x1.y - x3.y);
            float2 u0 = make_float2(t0.x + t1.x, t0.y + t1.y);
            float2 u2 = make_float2(t0.x - t1.x, t0.y - t1.y);
            float2 u1 = make_float2(t2.x + t3.y, t2.y - t3.x);   // t2 - i*t3
            float2 u3 = make_float2(t2.x - t3.y, t2.y + t3.x);   // t2 + i*t3
            int tj = q << (2 * s);                               // q * (N/L)
            z[base]         = u0;
            z[base +     m] = cmul(u1, tw[tj]);
            z[base + 2 * m] = cmul(u2, tw[(2 * tj) & 4095]);
            z[base + 3 * m] = cmul(u3, tw[(3 * tj) & 4095]);
        }
        __syncthreads();
    }

    // split packed spectrum, magnitudes for k = 1..2047 (twiddles now dead)
    float* mg = aux;   // mg[0..2047] signal0, mg[2048..4095] signal1
    for (int k = 1 + tid; k < 2048; k += 256) {
        int p1 = dr12(k), p2 = dr12(4096 - k);
        float2 Z1 = z[p1], Z2 = z[p2];
        float xr = 0.5f * (Z1.x + Z2.x), xi = 0.5f * (Z1.y - Z2.y);   // X(d0)
        float yr = 0.5f * (Z1.y + Z2.y), yi = 0.5f * (Z2.x - Z1.x);   // X(d0+1)
        mg[k]        = sqrtf(xr * xr + xi * xi);
        mg[2048 + k] = sqrtf(yr * yr + yi * yi);
    }
    __syncthreads();

    float* rv = aux + 4096;          // 256 floats
    int*   rk = (int*)(aux + 4352);  // 256 ints

    for (int s = 0; s < 2; s++) {
        float* m = mg + s * 2048;
        for (int r = 0; r < TOPK; r++) {
            float bv = -1.0f; int bk = 1 << 30;
            for (int k = 1 + tid; k < 2048; k += 256) {
                float v = m[k];
                if (v > bv || (v == bv && k < bk)) { bv = v; bk = k; }
            }
            rv[tid] = bv; rk[tid] = bk;
            __syncthreads();
            for (int off = 128; off > 0; off >>= 1) {
                if (tid < off) {
                    float ov = rv[tid + off]; int ok = rk[tid + off];
                    if (ov > rv[tid] || (ov == rv[tid] && ok < rk[tid])) {
                        rv[tid] = ov; rk[tid] = ok;
                    }
                }
                __syncthreads();
            }
            if (tid == 0) {
                int k = rk[0];
                int p1 = dr12(k), p2 = dr12(4096 - k);
                float2 Z1 = z[p1], Z2 = z[p2];
                float Xr, Xi;
                if (s == 0) { Xr = 0.5f * (Z1.x + Z2.x); Xi = 0.5f * (Z1.y - Z2.y); }
                else        { Xr = 0.5f * (Z1.y + Z2.y); Xi = 0.5f * (Z2.x - Z1.x); }
                int sig = b * 256 + d0 + s;
                d_pk [sig * TOPK + r] = k;
                d_pre[sig * TOPK + r] = Xr * (4.0f / 4096.0f);
                d_pim[sig * TOPK + r] = Xi * (4.0f / 4096.0f);
                m[k] = -2.0f;   // exclude from later rounds
            }
            __syncthreads();
        }
    }
}

// ---------------------------------------------------------------------------
// K2: reconstruction via table-exact rotation recurrence
//     out[b,t,d] = sum_j Re( C_j * e^{+2*pi*i*k_j*t/4096} )
// block = (32 d-lanes, 8 t-phases); each thread strides t by 8, 128 steps
// ---------------------------------------------------------------------------
__global__ void __launch_bounds__(256) k_recon(float* __restrict__ out) {
    int tx = threadIdx.x, ty = threadIdx.y;
    int d  = blockIdx.x * 32 + tx;
    int b  = blockIdx.y;
    int t0 = blockIdx.z * 1024 + ty;
    int sig = b * 256 + d;

    float xx[TOPK], yy[TOPK], cc[TOPK], ss[TOPK];
    #pragma unroll
    for (int j = 0; j < TOPK; j++) {
        int   k  = d_pk [sig * TOPK + j];
        float cr = d_pre[sig * TOPK + j];
        float ci = d_pim[sig * TOPK + j];
        float2 w0 = d_tw[(k * t0) & 4095];      // e^{-i*th0}
        float c0 = w0.x, s0 = -w0.y;            // e^{+i*th0}
        xx[j] = cr * c0 - ci * s0;              // Re/Im of C*e^{i*th0}
        yy[j] = cr * s0 + ci * c0;
        float2 w8 = d_tw[(8 * k) & 4095];       // e^{-i*8w}
        cc[j] = w8.x; ss[j] = -w8.y;            // e^{+i*8w}
    }

    float* po = out + ((size_t)b * 4096 + t0) * 256 + d;
    #pragma unroll 4
    for (int n = 0; n < 128; n++) {
        float acc = 0.0f;
        #pragma unroll
        for (int j = 0; j < TOPK; j++) acc += xx[j];
        po[(size_t)n * 8 * 256] = acc;
        #pragma unroll
        for (int j = 0; j < TOPK; j++) {
            float nx = xx[j] * cc[j] - yy[j] * ss[j];
            yy[j]    = xx[j] * ss[j] + yy[j] * cc[j];
            xx[j]    = nx;
        }
    }
}

// ---------------------------------------------------------------------------
extern "C" void kernel_launch(void* const* d_in, const int* in_sizes, int n_in,
                              void* d_out, int out_size) {
    (void)in_sizes; (void)n_in; (void)out_size;
    const float* x = (const float*)d_in[0];
    float* out = (float*)d_out;

    cudaFuncSetAttribute(k_fft, cudaFuncAttributeMaxDynamicSharedMemorySize, 65536);

    k_twiddle<<<16, 256>>>();

    dim3 gt(128, 8, 16), bt(32, 8);
    k_transpose<<<gt, bt>>>(x);

    k_fft<<<2048, 256, 65536>>>();

    dim3 gr(8, 16, 4), br(32, 8);
    k_recon<<<gr, br>>>(out);
}

// round 3
// speedup vs baseline: 1.6544x; 1.6544x over previous
#include <cuda_runtime.h>
#include <math.h>
#include <stdint.h>

#define T_LEN 4096
#define NSIG  4096          // 16 * 256 signals
#define TOPK  7

// -------- scratch (module-scope device memory; no runtime allocation) -------
__device__ float2 d_tw[T_LEN];                  // e^{-2*pi*i*j/4096}
__device__ float  d_xT[16 * 256 * 4096];        // transposed input (b,d,t)
__device__ int    d_pk [NSIG * TOPK];           // selected frequency index k
__device__ float  d_pre[NSIG * TOPK];           // coefficient real = 4*Re(X)/T
__device__ float  d_pim[NSIG * TOPK];           // coefficient imag = 4*Im(X)/T

// W16^e = (cos(pi*e/8), -sin(pi*e/8)), e = 0..9
__constant__ float2 W16C[10] = {
    { 1.0f, 0.0f},
    { 0.92387953251128674f, -0.38268343236508978f},
    { 0.70710678118654752f, -0.70710678118654752f},
    { 0.38268343236508978f, -0.92387953251128674f},
    { 0.0f, -1.0f},
    { 0.0f,  0.0f},   // unused
    {-0.70710678118654752f, -0.70710678118654752f},
    { 0.0f,  0.0f},   // unused
    { 0.0f,  0.0f},   // unused
    {-0.92387953251128674f,  0.38268343236508978f},
};

// ---------------------------------------------------------------------------
// K0: twiddle table in double precision (exact-ish regardless of fast-math)
// ---------------------------------------------------------------------------
__global__ void k_twiddle() {
    int j = blockIdx.x * blockDim.x + threadIdx.x;
    if (j < T_LEN) {
        double a = -2.0 * 3.14159265358979323846 * (double)j / 4096.0;
        d_tw[j] = make_float2((float)cos(a), (float)sin(a));
    }
}

// ---------------------------------------------------------------------------
// KT: (16,4096,256) -> (16,256,4096) tiled transpose, fully coalesced
// ---------------------------------------------------------------------------
__global__ void __launch_bounds__(256) k_transpose(const float* __restrict__ x) {
    __shared__ float tile[32][33];
    int b  = blockIdx.z;
    int t0 = blockIdx.x * 32;
    int d0 = blockIdx.y * 32;
    #pragma unroll
    for (int r = threadIdx.y; r < 32; r += 8)
        tile[r][threadIdx.x] =
            x[((size_t)b * 4096 + t0 + r) * 256 + d0 + threadIdx.x];
    __syncthreads();
    #pragma unroll
    for (int r = threadIdx.y; r < 32; r += 8)
        d_xT[((size_t)b * 256 + d0 + r) * 4096 + t0 + threadIdx.x] =
            tile[threadIdx.x][r];
}

// ---------------------------------------------------------------------------
// complex helpers
// ---------------------------------------------------------------------------
__device__ __forceinline__ float2 cmul(float2 a, float2 b) {
    return make_float2(a.x * b.x - a.y * b.y, a.x * b.y + a.y * b.x);
}
__device__ __forceinline__ float2 cadd(float2 a, float2 b) { return make_float2(a.x + b.x, a.y + b.y); }
__device__ __forceinline__ float2 csub(float2 a, float2 b) { return make_float2(a.x - b.x, a.y - b.y); }
__device__ __forceinline__ float2 mnegi(float2 a) { return make_float2(a.y, -a.x); }  // -i * a

// 16-point DFT, natural order in -> natural order out, all in registers.
// Y[j] = sum_r v[r] * W16^{r*j}
__device__ __forceinline__ void dft16(float2 v[16]) {
    float2 t[16];
    #pragma unroll
    for (int r0 = 0; r0 < 4; r0++) {
        float2 a0 = v[r0], a1 = v[r0 + 4], a2 = v[r0 + 8], a3 = v[r0 + 12];
        float2 s02 = cadd(a0, a2), d02 = csub(a0, a2);
        float2 s13 = cadd(a1, a3), d13 = csub(a1, a3);
        float2 id13 = mnegi(d13);
        t[r0 * 4 + 0] = cadd(s02, s13);
        t[r0 * 4 + 1] = cadd(d02, id13);
        t[r0 * 4 + 2] = csub(s02, s13);
        t[r0 * 4 + 3] = csub(d02, id13);
    }
    #pragma unroll
    for (int r0 = 1; r0 < 4; r0++)
        #pragma unroll
        for (int j0 = 1; j0 < 4; j0++)
            t[r0 * 4 + j0] = cmul(t[r0 * 4 + j0], W16C[r0 * j0]);
    #pragma unroll
    for (int j0 = 0; j0 < 4; j0++) {
        float2 a0 = t[j0], a1 = t[4 + j0], a2 = t[8 + j0], a3 = t[12 + j0];
        float2 s02 = cadd(a0, a2), d02 = csub(a0, a2);
        float2 s13 = cadd(a1, a3), d13 = csub(a1, a3);
        float2 id13 = mnegi(d13);
        v[j0 + 0]  = cadd(s02, s13);
        v[j0 + 4]  = cadd(d02, id13);
        v[j0 + 8]  = csub(s02, s13);
        v[j0 + 12] = csub(d02, id13);
    }
}

// ---------------------------------------------------------------------------
// K1: 4096 = 16^3 self-sorting FFT (2 real signals packed), then top-7.
// Smem: two padded transpose buffers (16*272 float2 each). Conflict-free:
// every 16-lane access phase uses stride-1 or stride-17 (odd) float2 indexing.
// ---------------------------------------------------------------------------
__global__ void __launch_bounds__(256) k_fft() {
    extern __shared__ float2 sm[];
    float2* sY = sm;            // 4352 float2 (stage1->2 buf, later spectrum X)
    float2* sZ = sm + 4352;     // 4352 float2 (stage2->3 buf, later magnitudes)

    int tid = threadIdx.x;
    int b   = blockIdx.x >> 7;
    int d0  = (blockIdx.x & 127) << 1;

    const float* r0p = d_xT + ((size_t)b * 256 + d0) * 4096;
    const float* r1p = r0p + 4096;

    float2 v[16];

    // ---- stage 1: a = tid; y1[a,j] = DFT16_r(x[a+256r]) * W4096^{a*j} ----
    {
        int a = tid;
        #pragma unroll
        for (int r = 0; r < 16; r++)
            v[r] = make_float2(r0p[a + 256 * r], r1p[a + 256 * r]);
        dft16(v);
        float2 w = d_tw[a];
        float2 p = w;
        #pragma unroll
        for (int j = 1; j < 16; j++) { v[j] = cmul(v[j], p); p = cmul(p, w); }
        int c = a >> 4, bb = a & 15;
        #pragma unroll
        for (int j = 0; j < 16; j++)
            sY[j * 272 + c * 17 + bb] = v[j];
    }
    __syncthreads();

    // ---- stage 2: (j,b); y2 = DFT16_c(Y[j][b+16c]) * W256^{b*i} ----
    {
        int j = tid >> 4, bb = tid & 15;
        #pragma unroll
        for (int c = 0; c < 16; c++) v[c] = sY[j * 272 + c * 17 + bb];
        dft16(v);
        float2 w = d_tw[16 * bb];
        float2 p = w;
        #pragma unroll
        for (int i = 1; i < 16; i++) { v[i] = cmul(v[i], p); p = cmul(p, w); }
        #pragma unroll
        for (int i = 0; i < 16; i++) sZ[j * 272 + i * 17 + bb] = v[i];
    }
    __syncthreads();

    // ---- stage 3: (j,i); X[j+16i+256l] = DFT16_b(Z[j][i][b]) ----
    // write spectrum into sY at xidx(k) = k + (k>>4)  (= j + 17i + 272l)
    {
        int j = tid >> 4, i = tid & 15;
        #pragma unroll
        for (int bb = 0; bb < 16; bb++) v[bb] = sZ[j * 272 + i * 17 + bb];
        dft16(v);
        #pragma unroll
        for (int l = 0; l < 16; l++)
            sY[j + 17 * i + 272 * l] = v[l];
    }
    __syncthreads();

    // ---- magnitudes: unpack 2 real spectra, k = 1..2047 ----
    float* mg = (float*)sZ;     // [0..2047] sig0, [2048..4095] sig1
    for (int k = 1 + tid; k < 2048; k += 256) {
        float2 Z1 = sY[k + (k >> 4)];
        int k2 = 4096 - k;
        float2 Z2 = sY[k2 + (k2 >> 4)];
        float xr = 0.5f * (Z1.x + Z2.x), xi = 0.5f * (Z1.y - Z2.y);
        float yr = 0.5f * (Z1.y + Z2.y), yi = 0.5f * (Z2.x - Z1.x);
        mg[k]        = sqrtf(xr * xr + xi * xi);
        mg[2048 + k] = sqrtf(yr * yr + yi * yi);
    }
    __syncthreads();

    // ---- top-7: warps 0-3 -> signal 0, warps 4-7 -> signal 1 ----
    int s    = tid >> 7;        // which signal this half-block handles
    int lid  = tid & 127;
    int wid  = tid >> 5;
    int lane = tid & 31;
    float* m  = mg + s * 2048;
    float* cv = mg + 4096;              // 8 floats scratch
    int*   ck = (int*)(mg + 4104);      // 8 ints scratch

    for (int r = 0; r < TOPK; r++) {
        float bv = -1.0f; int bk = 1 << 30;
        for (int k = 1 + lid; k < 2048; k += 128) {
            float vv = m[k];
            if (vv > bv || (vv == bv && k < bk)) { bv = vv; bk = k; }
        }
        #pragma unroll
        for (int off = 16; off; off >>= 1) {
            float ov = __shfl_down_sync(0xffffffffu, bv, off);
            int   ok = __shfl_down_sync(0xffffffffu, bk, off);
            if (ov > bv || (ov == bv && ok < bk)) { bv = ov; bk = ok; }
        }
        if (lane == 0) { cv[wid] = bv; ck[wid] = bk; }
        __syncthreads();
        if (lid == 0) {
            float Bv = cv[s * 4]; int Bk = ck[s * 4];
            #pragma unroll
            for (int w = 1; w < 4; w++) {
                float ov = cv[s * 4 + w]; int ok = ck[s * 4 + w];
                if (ov > Bv || (ov == Bv && ok < Bk)) { Bv = ov; Bk = ok; }
            }
            int k = Bk;
            float2 Z1 = sY[k + (k >> 4)];
            int k2 = 4096 - k;
            float2 Z2 = sY[k2 + (k2 >> 4)];
            float Xr, Xi;
            if (s == 0) { Xr = 0.5f * (Z1.x + Z2.x); Xi = 0.5f * (Z1.y - Z2.y); }
            else        { Xr = 0.5f * (Z1.y + Z2.y); Xi = 0.5f * (Z2.x - Z1.x); }
            int sig = b * 256 + d0 + s;
            d_pk [sig * TOPK + r] = k;
            d_pre[sig * TOPK + r] = Xr * (4.0f / 4096.0f);
            d_pim[sig * TOPK + r] = Xi * (4.0f / 4096.0f);
            m[k] = -1.0f;    // exclude from later rounds
        }
        __syncthreads();
    }
}

// ---------------------------------------------------------------------------
// K2: reconstruction via Chebyshev 3-term recurrence (step = 8 samples)
//     p_n = 2*cos(8w)*p_{n-1} - p_{n-2}, exact-table seeds.
// block = (32 d-lanes, 8 t-phases); each thread strides t by 8, 128 outputs.
// ---------------------------------------------------------------------------
__global__ void __launch_bounds__(256) k_recon(float* __restrict__ out) {
    int tx = threadIdx.x, ty = threadIdx.y;
    int d   = blockIdx.x * 32 + tx;
    int b   = blockIdx.y;
    int t0  = blockIdx.z * 1024 + ty;
    int sig = b * 256 + d;

    float p0[TOPK], p1[TOPK], c2[TOPK];
    #pragma unroll
    for (int j = 0; j < TOPK; j++) {
        int   k  = d_pk [sig * TOPK + j];
        float cr = d_pre[sig * TOPK + j];
        float ci = d_pim[sig * TOPK + j];
        float2 w0 = d_tw[(k * t0) & 4095];        // (cos, -sin) of w*t0
        p0[j] = cr * w0.x + ci * w0.y;            // Re(C * e^{i w t0})
        float2 w1 = d_tw[(k * (t0 + 8)) & 4095];
        p1[j] = cr * w1.x + ci * w1.y;
        c2[j] = 2.0f * d_tw[(8 * k) & 4095].x;    // 2*cos(8w)
    }

    float* po = out + ((size_t)b * 4096 + t0) * 256 + d;
    float a0 = 0.0f, a1 = 0.0f;
    #pragma unroll
    for (int j = 0; j < TOPK; j++) { a0 += p0[j]; a1 += p1[j]; }
    po[0] = a0;
    po[2048] = a1;    // 8 * 256

    #pragma unroll 4
    for (int n = 2; n < 128; n += 2) {
        float s0 = 0.0f, s1 = 0.0f;
        #pragma unroll
        for (int j = 0; j < TOPK; j++) {
            p0[j] = c2[j] * p1[j] - p0[j];
            s0 += p0[j];
        }
        po[(size_t)n * 2048] = s0;
        #pragma unroll
        for (int j = 0; j < TOPK; j++) {
            p1[j] = c2[j] * p0[j] - p1[j];
            s1 += p1[j];
        }
        po[(size_t)(n + 1) * 2048] = s1;
    }
}

// ---------------------------------------------------------------------------
extern "C" void kernel_launch(void* const* d_in, const int* in_sizes, int n_in,
                              void* d_out, int out_size) {
    (void)in_sizes; (void)n_in; (void)out_size;
    const float* x = (const float*)d_in[0];
    float* out = (float*)d_out;

    cudaFuncSetAttribute(k_fft, cudaFuncAttributeMaxDynamicSharedMemorySize, 69632);

    k_twiddle<<<16, 256>>>();

    dim3 gt(128, 8, 16), bt(32, 8);
    k_transpose<<<gt, bt>>>(x);

    k_fft<<<2048, 256, 69632>>>();

    dim3 gr(8, 16, 4), br(32, 8);
    k_recon<<<gr, br>>>(out);
}

// round 4
// speedup vs baseline: 2.4868x; 1.5031x over previous
#include <cuda_runtime.h>
#include <math.h>
#include <stdint.h>

#define T_LEN 4096
#define NSIG  4096          // 16 * 256 signals
#define TOPK  7

// -------- scratch (module-scope device memory; no runtime allocation) -------
__device__ float2 d_tw[T_LEN];                  // e^{-2*pi*i*j/4096}
__device__ float  d_xT[16 * 256 * 4096];        // transposed input (b,d,t)
__device__ int    d_pk [NSIG * TOPK];           // selected frequency index k
__device__ float  d_pre[NSIG * TOPK];           // coefficient real = 4*Re(X)/T
__device__ float  d_pim[NSIG * TOPK];           // coefficient imag = 4*Im(X)/T

// W16^e = (cos(pi*e/8), -sin(pi*e/8)), e = 0..9
__constant__ float2 W16C[10] = {
    { 1.0f, 0.0f},
    { 0.92387953251128674f, -0.38268343236508978f},
    { 0.70710678118654752f, -0.70710678118654752f},
    { 0.38268343236508978f, -0.92387953251128674f},
    { 0.0f, -1.0f},
    { 0.0f,  0.0f},   // unused
    {-0.70710678118654752f, -0.70710678118654752f},
    { 0.0f,  0.0f},   // unused
    { 0.0f,  0.0f},   // unused
    {-0.92387953251128674f,  0.38268343236508978f},
};

// ---------------------------------------------------------------------------
// K0: twiddle table in double precision (exact-ish regardless of fast-math)
// ---------------------------------------------------------------------------
__global__ void k_twiddle() {
    int j = blockIdx.x * blockDim.x + threadIdx.x;
    if (j < T_LEN) {
        double a = -2.0 * 3.14159265358979323846 * (double)j / 4096.0;
        d_tw[j] = make_float2((float)cos(a), (float)sin(a));
    }
}

// ---------------------------------------------------------------------------
// KT: (16,4096,256) -> (16,256,4096) tiled transpose, fully coalesced
// ---------------------------------------------------------------------------
__global__ void __launch_bounds__(256) k_transpose(const float* __restrict__ x) {
    __shared__ float tile[32][33];
    int b  = blockIdx.z;
    int t0 = blockIdx.x * 32;
    int d0 = blockIdx.y * 32;
    #pragma unroll
    for (int r = threadIdx.y; r < 32; r += 8)
        tile[r][threadIdx.x] =
            x[((size_t)b * 4096 + t0 + r) * 256 + d0 + threadIdx.x];
    __syncthreads();
    #pragma unroll
    for (int r = threadIdx.y; r < 32; r += 8)
        d_xT[((size_t)b * 256 + d0 + r) * 4096 + t0 + threadIdx.x] =
            tile[threadIdx.x][r];
}

// ---------------------------------------------------------------------------
// complex helpers
// ---------------------------------------------------------------------------
__device__ __forceinline__ float2 cmul(float2 a, float2 b) {
    return make_float2(a.x * b.x - a.y * b.y, a.x * b.y + a.y * b.x);
}
__device__ __forceinline__ float2 cadd(float2 a, float2 b) { return make_float2(a.x + b.x, a.y + b.y); }
__device__ __forceinline__ float2 csub(float2 a, float2 b) { return make_float2(a.x - b.x, a.y - b.y); }
__device__ __forceinline__ float2 mnegi(float2 a) { return make_float2(a.y, -a.x); }  // -i * a

// In-place 16-point DFT: two radix-4 passes, NO temp array.
// After the call, Y[j] lives at slot YSLOT(j) = 4*(j&3) + (j>>2).
#define YSLOT(j) (4 * ((j) & 3) + ((j) >> 2))
__device__ __forceinline__ void dft16_ip(float2 v[16]) {
    #pragma unroll
    for (int m = 0; m < 4; m++) {
        float2 a0 = v[m], a1 = v[m + 4], a2 = v[m + 8], a3 = v[m + 12];
        float2 s02 = cadd(a0, a2), d02 = csub(a0, a2);
        float2 s13 = cadd(a1, a3), d13 = csub(a1, a3);
        float2 id  = mnegi(d13);
        v[m]      = cadd(s02, s13);
        v[m + 4]  = cadd(d02, id);
        v[m + 8]  = csub(s02, s13);
        v[m + 12] = csub(d02, id);
    }
    #pragma unroll
    for (int j1 = 1; j1 < 4; j1++)
        #pragma unroll
        for (int m = 1; m < 4; m++)
            v[m + 4 * j1] = cmul(v[m + 4 * j1], W16C[m * j1]);
    #pragma unroll
    for (int g = 0; g < 4; g++) {
        float2 a0 = v[4*g], a1 = v[4*g + 1], a2 = v[4*g + 2], a3 = v[4*g + 3];
        float2 s02 = cadd(a0, a2), d02 = csub(a0, a2);
        float2 s13 = cadd(a1, a3), d13 = csub(a1, a3);
        float2 id  = mnegi(d13);
        v[4*g]     = cadd(s02, s13);
        v[4*g + 1] = cadd(d02, id);
        v[4*g + 2] = csub(s02, s13);
        v[4*g + 3] = csub(d02, id);
    }
}

// ---------------------------------------------------------------------------
// K1: 4096 = 16^3 self-sorting FFT (2 real signals packed), then top-7.
// Single padded smem buffer (16*272 float2) reused across all 3 stages,
// plus a separate magnitude region. 50.1 KB total -> 3 blocks/SM.
// ---------------------------------------------------------------------------
__global__ void __launch_bounds__(256, 3) k_fft() {
    extern __shared__ char smraw[];
    float2* sY = (float2*)smraw;                 // 4352 float2 (34816 B)
    float*  mg = (float*)(smraw + 34816);        // 4096 floats (16384 B)
    float*  cv = (float*)(smraw + 34816 + 16384);          // 8 floats
    int*    ck = (int*)  (smraw + 34816 + 16384 + 32);     // 8 ints

    int tid = threadIdx.x;
    int b   = blockIdx.x >> 7;
    int d0  = (blockIdx.x & 127) << 1;

    const float* r0p = d_xT + ((size_t)b * 256 + d0) * 4096;
    const float* r1p = r0p + 4096;

    float2 v[16];

    // ---- stage 1: a = tid; y1[a,j] = DFT16_r(x[a+256r]) * W4096^{a*j} ----
    {
        int a = tid;
        #pragma unroll
        for (int r = 0; r < 16; r++)
            v[r] = make_float2(r0p[a + 256 * r], r1p[a + 256 * r]);
        dft16_ip(v);
        int c = a >> 4, bb = a & 15;
        float2 w = d_tw[a];
        float2 p = w;
        sY[0 * 272 + c * 17 + bb] = v[YSLOT(0)];
        #pragma unroll
        for (int j = 1; j < 16; j++) {
            sY[j * 272 + c * 17 + bb] = cmul(v[YSLOT(j)], p);
            p = cmul(p, w);
        }
    }
    __syncthreads();

    // ---- stage 2 (in place; each thread owns its address set) ----
    {
        int j = tid >> 4, bb = tid & 15;
        int base = j * 272 + bb;
        #pragma unroll
        for (int c = 0; c < 16; c++) v[c] = sY[base + c * 17];
        dft16_ip(v);
        float2 w = d_tw[16 * bb];
        float2 p = w;
        sY[base] = v[YSLOT(0)];
        #pragma unroll
        for (int i = 1; i < 16; i++) {
            sY[base + i * 17] = cmul(v[YSLOT(i)], p);
            p = cmul(p, w);
        }
    }
    __syncthreads();

    // ---- stage 3: read own set into regs, sync, scatter spectrum ----
    {
        int j = tid >> 4, i = tid & 15;
        #pragma unroll
        for (int bb = 0; bb < 16; bb++) v[bb] = sY[j * 272 + i * 17 + bb];
        dft16_ip(v);
        __syncthreads();
        // X[k], k = j+16i+256l, stored at k + (k>>4) = j + 17i + 272l
        #pragma unroll
        for (int l = 0; l < 16; l++)
            sY[j + 17 * i + 272 * l] = v[YSLOT(l)];
    }
    __syncthreads();

    // ---- magnitudes: unpack 2 real spectra, k = 1..2047 ----
    for (int k = 1 + tid; k < 2048; k += 256) {
        float2 Z1 = sY[k + (k >> 4)];
        int k2 = 4096 - k;
        float2 Z2 = sY[k2 + (k2 >> 4)];
        float xr = 0.5f * (Z1.x + Z2.x), xi = 0.5f * (Z1.y - Z2.y);
        float yr = 0.5f * (Z1.y + Z2.y), yi = 0.5f * (Z2.x - Z1.x);
        mg[k]        = sqrtf(xr * xr + xi * xi);
        mg[2048 + k] = sqrtf(yr * yr + yi * yi);
    }
    __syncthreads();

    // ---- top-7: warps 0-3 -> signal 0, warps 4-7 -> signal 1 ----
    int s    = tid >> 7;
    int lid  = tid & 127;
    int wid  = tid >> 5;
    int lane = tid & 31;
    float* m = mg + s * 2048;

    for (int r = 0; r < TOPK; r++) {
        float bv = -1.0f; int bk = 1 << 30;
        for (int k = 1 + lid; k < 2048; k += 128) {
            float vv = m[k];
            if (vv > bv || (vv == bv && k < bk)) { bv = vv; bk = k; }
        }
        #pragma unroll
        for (int off = 16; off; off >>= 1) {
            float ov = __shfl_down_sync(0xffffffffu, bv, off);
            int   ok = __shfl_down_sync(0xffffffffu, bk, off);
            if (ov > bv || (ov == bv && ok < bk)) { bv = ov; bk = ok; }
        }
        if (lane == 0) { cv[wid] = bv; ck[wid] = bk; }
        __syncthreads();
        if (lid == 0) {
            float Bv = cv[s * 4]; int Bk = ck[s * 4];
            #pragma unroll
            for (int w = 1; w < 4; w++) {
                float ov = cv[s * 4 + w]; int ok = ck[s * 4 + w];
                if (ov > Bv || (ov == Bv && ok < Bk)) { Bv = ov; Bk = ok; }
            }
            int k = Bk;
            float2 Z1 = sY[k + (k >> 4)];
            int k2 = 4096 - k;
            float2 Z2 = sY[k2 + (k2 >> 4)];
            float Xr, Xi;
            if (s == 0) { Xr = 0.5f * (Z1.x + Z2.x); Xi = 0.5f * (Z1.y - Z2.y); }
            else        { Xr = 0.5f * (Z1.y + Z2.y); Xi = 0.5f * (Z2.x - Z1.x); }
            int sig = b * 256 + d0 + s;
            d_pk [sig * TOPK + r] = k;
            d_pre[sig * TOPK + r] = Xr * (4.0f / 4096.0f);
            d_pim[sig * TOPK + r] = Xi * (4.0f / 4096.0f);
            m[k] = -1.0f;    // exclude from later rounds
        }
        __syncthreads();
    }
}

// ---------------------------------------------------------------------------
// K2: reconstruction via Chebyshev 3-term recurrence (step = 8 samples)
//     p_n = 2*cos(8w)*p_{n-1} - p_{n-2}, exact-table seeds.
// block = (32 d-lanes, 8 t-phases); thread strides t by 8, 64 outputs.
// ---------------------------------------------------------------------------
__global__ void __launch_bounds__(256) k_recon(float* __restrict__ out) {
    int tx = threadIdx.x, ty = threadIdx.y;
    int d   = blockIdx.x * 32 + tx;
    int b   = blockIdx.y;
    int t0  = blockIdx.z * 512 + ty;
    int sig = b * 256 + d;

    float p0[TOPK], p1[TOPK], c2[TOPK];
    #pragma unroll
    for (int j = 0; j < TOPK; j++) {
        int   k  = d_pk [sig * TOPK + j];
        float cr = d_pre[sig * TOPK + j];
        float ci = d_pim[sig * TOPK + j];
        float2 w0 = d_tw[(k * t0) & 4095];        // (cos, -sin) of w*t0
        p0[j] = cr * w0.x + ci * w0.y;            // Re(C * e^{i w t0})
        float2 w1 = d_tw[(k * (t0 + 8)) & 4095];
        p1[j] = cr * w1.x + ci * w1.y;
        c2[j] = 2.0f * d_tw[(8 * k) & 4095].x;    // 2*cos(8w)
    }

    float* po = out + ((size_t)b * 4096 + t0) * 256 + d;
    {
        float a0 = ((p0[0] + p0[1]) + (p0[2] + p0[3])) + ((p0[4] + p0[5]) + p0[6]);
        float a1 = ((p1[0] + p1[1]) + (p1[2] + p1[3])) + ((p1[4] + p1[5]) + p1[6]);
        po[0]    = a0;
        po[2048] = a1;    // 8 * 256
    }

    #pragma unroll 4
    for (int n = 2; n < 64; n += 2) {
        #pragma unroll
        for (int j = 0; j < TOPK; j++) p0[j] = c2[j] * p1[j] - p0[j];
        po[(size_t)n * 2048] =
            ((p0[0] + p0[1]) + (p0[2] + p0[3])) + ((p0[4] + p0[5]) + p0[6]);
        #pragma unroll
        for (int j = 0; j < TOPK; j++) p1[j] = c2[j] * p0[j] - p1[j];
        po[(size_t)(n + 1) * 2048] =
            ((p1[0] + p1[1]) + (p1[2] + p1[3])) + ((p1[4] + p1[5]) + p1[6]);
    }
}

// ---------------------------------------------------------------------------
extern "C" void kernel_launch(void* const* d_in, const int* in_sizes, int n_in,
                              void* d_out, int out_size) {
    (void)in_sizes; (void)n_in; (void)out_size;
    const float* x = (const float*)d_in[0];
    float* out = (float*)d_out;

    cudaFuncSetAttribute(k_fft, cudaFuncAttributeMaxDynamicSharedMemorySize, 51264);

    k_twiddle<<<16, 256>>>();

    dim3 gt(128, 8, 16), bt(32, 8);
    k_transpose<<<gt, bt>>>(x);

    k_fft<<<2048, 256, 51264>>>();

    dim3 gr(8, 16, 8), br(32, 8);
    k_recon<<<gr, br>>>(out);
}

// round 5
// speedup vs baseline: 2.9661x; 1.1927x over previous
#include <cuda_runtime.h>
#include <math.h>
#include <stdint.h>

#define T_LEN 4096
#define NSIG  4096          // 16 * 256 signals
#define TOPK  7

// -------- scratch (module-scope device memory; no runtime allocation) -------
__device__ float2 d_tw[T_LEN];                  // e^{-2*pi*i*j/4096}
__device__ float  d_xT[16 * 256 * 4096];        // transposed input (b,d,t)
__device__ int    d_pk [NSIG * TOPK];           // selected frequency index k
__device__ float  d_pre[NSIG * TOPK];           // coefficient real = 4*Re(X)/T
__device__ float  d_pim[NSIG * TOPK];           // coefficient imag = 4*Im(X)/T

// W16^e = (cos(pi*e/8), -sin(pi*e/8)), e = 0..9
__constant__ float2 W16C[10] = {
    { 1.0f, 0.0f},
    { 0.92387953251128674f, -0.38268343236508978f},
    { 0.70710678118654752f, -0.70710678118654752f},
    { 0.38268343236508978f, -0.92387953251128674f},
    { 0.0f, -1.0f},
    { 0.0f,  0.0f},   // unused
    {-0.70710678118654752f, -0.70710678118654752f},
    { 0.0f,  0.0f},   // unused
    { 0.0f,  0.0f},   // unused
    {-0.92387953251128674f,  0.38268343236508978f},
};

// ---------------------------------------------------------------------------
// K0: twiddle table in double precision (exact-ish regardless of fast-math)
// ---------------------------------------------------------------------------
__global__ void k_twiddle() {
    int j = blockIdx.x * blockDim.x + threadIdx.x;
    if (j < T_LEN) {
        double a = -2.0 * 3.14159265358979323846 * (double)j / 4096.0;
        d_tw[j] = make_float2((float)cos(a), (float)sin(a));
    }
}

// ---------------------------------------------------------------------------
// KT: (16,4096,256) -> (16,256,4096) tiled transpose, fully coalesced
// ---------------------------------------------------------------------------
__global__ void __launch_bounds__(256) k_transpose(const float* __restrict__ x) {
    __shared__ float tile[32][33];
    int b  = blockIdx.z;
    int t0 = blockIdx.x * 32;
    int d0 = blockIdx.y * 32;
    #pragma unroll
    for (int r = threadIdx.y; r < 32; r += 8)
        tile[r][threadIdx.x] =
            x[((size_t)b * 4096 + t0 + r) * 256 + d0 + threadIdx.x];
    __syncthreads();
    #pragma unroll
    for (int r = threadIdx.y; r < 32; r += 8)
        d_xT[((size_t)b * 256 + d0 + r) * 4096 + t0 + threadIdx.x] =
            tile[threadIdx.x][r];
}

// ---------------------------------------------------------------------------
// complex helpers
// ---------------------------------------------------------------------------
__device__ __forceinline__ float2 cmul(float2 a, float2 b) {
    return make_float2(a.x * b.x - a.y * b.y, a.x * b.y + a.y * b.x);
}
__device__ __forceinline__ float2 cadd(float2 a, float2 b) { return make_float2(a.x + b.x, a.y + b.y); }
__device__ __forceinline__ float2 csub(float2 a, float2 b) { return make_float2(a.x - b.x, a.y - b.y); }
__device__ __forceinline__ float2 mnegi(float2 a) { return make_float2(a.y, -a.x); }  // -i * a

// In-place 16-point DFT: two radix-4 passes, NO temp array.
// After the call, Y[j] lives at slot YSLOT(j) = 4*(j&3) + (j>>2).
#define YSLOT(j) (4 * ((j) & 3) + ((j) >> 2))
__device__ __forceinline__ void dft16_ip(float2 v[16]) {
    #pragma unroll
    for (int m = 0; m < 4; m++) {
        float2 a0 = v[m], a1 = v[m + 4], a2 = v[m + 8], a3 = v[m + 12];
        float2 s02 = cadd(a0, a2), d02 = csub(a0, a2);
        float2 s13 = cadd(a1, a3), d13 = csub(a1, a3);
        float2 id  = mnegi(d13);
        v[m]      = cadd(s02, s13);
        v[m + 4]  = cadd(d02, id);
        v[m + 8]  = csub(s02, s13);
        v[m + 12] = csub(d02, id);
    }
    #pragma unroll
    for (int j1 = 1; j1 < 4; j1++)
        #pragma unroll
        for (int m = 1; m < 4; m++)
            v[m + 4 * j1] = cmul(v[m + 4 * j1], W16C[m * j1]);
    #pragma unroll
    for (int g = 0; g < 4; g++) {
        float2 a0 = v[4*g], a1 = v[4*g + 1], a2 = v[4*g + 2], a3 = v[4*g + 3];
        float2 s02 = cadd(a0, a2), d02 = csub(a0, a2);
        float2 s13 = cadd(a1, a3), d13 = csub(a1, a3);
        float2 id  = mnegi(d13);
        v[4*g]     = cadd(s02, s13);
        v[4*g + 1] = cadd(d02, id);
        v[4*g + 2] = csub(s02, s13);
        v[4*g + 3] = csub(d02, id);
    }
}

// ---------------------------------------------------------------------------
// K1: 4096 = 16^3 self-sorting FFT (2 real signals packed), then top-7 on
// register-resident squared magnitudes (no sqrt, no magnitude smem buffer).
// Smem: one padded buffer (16*272 float2 = 34816 B) + 72 B scratch.
// ---------------------------------------------------------------------------
__global__ void __launch_bounds__(256, 3) k_fft() {
    extern __shared__ char smraw[];
    float2* sY = (float2*)smraw;                 // 4352 float2 (34816 B)
    float*  cv = (float*)(smraw + 34816);        // 8 floats
    int*    ck = (int*)  (smraw + 34816 + 32);   // 8 ints
    int*    kb = (int*)  (smraw + 34816 + 64);   // 2 ints (winner broadcast)

    int tid = threadIdx.x;
    int b   = blockIdx.x >> 7;
    int d0  = (blockIdx.x & 127) << 1;

    const float* r0p = d_xT + ((size_t)b * 256 + d0) * 4096;
    const float* r1p = r0p + 4096;

    float2 v[16];

    // ---- stage 1: a = tid; y1[a,j] = DFT16_r(x[a+256r]) * W4096^{a*j} ----
    {
        int a = tid;
        #pragma unroll
        for (int r = 0; r < 16; r++)
            v[r] = make_float2(r0p[a + 256 * r], r1p[a + 256 * r]);
        dft16_ip(v);
        int c = a >> 4, bb = a & 15;
        float2 w = d_tw[a];
        float2 p = w;
        sY[0 * 272 + c * 17 + bb] = v[YSLOT(0)];
        #pragma unroll
        for (int j = 1; j < 16; j++) {
            sY[j * 272 + c * 17 + bb] = cmul(v[YSLOT(j)], p);
            p = cmul(p, w);
        }
    }
    __syncthreads();

    // ---- stage 2 (in place; each thread owns its address set) ----
    {
        int j = tid >> 4, bb = tid & 15;
        int base = j * 272 + bb;
        #pragma unroll
        for (int c = 0; c < 16; c++) v[c] = sY[base + c * 17];
        dft16_ip(v);
        float2 w = d_tw[16 * bb];
        float2 p = w;
        sY[base] = v[YSLOT(0)];
        #pragma unroll
        for (int i = 1; i < 16; i++) {
            sY[base + i * 17] = cmul(v[YSLOT(i)], p);
            p = cmul(p, w);
        }
    }
    __syncthreads();

    // ---- stage 3: read own set into regs, sync, scatter spectrum ----
    {
        int j = tid >> 4, i = tid & 15;
        #pragma unroll
        for (int bb = 0; bb < 16; bb++) v[bb] = sY[j * 272 + i * 17 + bb];
        dft16_ip(v);
        __syncthreads();
        // X[k], k = j+16i+256l, stored at k + (k>>4) = j + 17i + 272l
        #pragma unroll
        for (int l = 0; l < 16; l++)
            sY[j + 17 * i + 272 * l] = v[YSLOT(l)];
    }
    __syncthreads();

    // ---- top-7 on squared magnitudes, register-resident ----
    // warps 0-3 -> signal 0, warps 4-7 -> signal 1; lane lid owns
    // k = 1 + lid + 128*i for i = 0..15 (k = 2048 slot invalidated).
    int s    = tid >> 7;
    int lid  = tid & 127;
    int wid  = tid >> 5;
    int lane = tid & 31;

    float mv[16];
    #pragma unroll
    for (int i = 0; i < 16; i++) {
        int k = 1 + lid + 128 * i;
        float m2 = -1.0f;
        if (k < 2048) {
            float2 Z1 = sY[k + (k >> 4)];
            int k2 = 4096 - k;
            float2 Z2 = sY[k2 + (k2 >> 4)];
            float xr, xi;
            if (s == 0) { xr = Z1.x + Z2.x; xi = Z1.y - Z2.y; }
            else        { xr = Z1.y + Z2.y; xi = Z2.x - Z1.x; }
            m2 = xr * xr + xi * xi;     // 4*|X|^2 (monotone in |X|)
        }
        mv[i] = m2;
    }

    // persistent per-lane best (strict > keeps lowest k within a lane)
    float bv = -2.0f; int bk = 1 << 30;
    #pragma unroll
    for (int i = 0; i < 16; i++)
        if (mv[i] > bv) { bv = mv[i]; bk = 1 + lid + 128 * i; }

    for (int r = 0; r < TOPK; r++) {
        // warp-level reduction (non-destructive copies)
        float rv = bv; int rk = bk;
        #pragma unroll
        for (int off = 16; off; off >>= 1) {
            float ov = __shfl_down_sync(0xffffffffu, rv, off);
            int   ok = __shfl_down_sync(0xffffffffu, rk, off);
            if (ov > rv || (ov == rv && ok < rk)) { rv = ov; rk = ok; }
        }
        if (lane == 0) { cv[wid] = rv; ck[wid] = rk; }
        __syncthreads();
        if (lid == 0) {
            float Bv = cv[s * 4]; int Bk = ck[s * 4];
            #pragma unroll
            for (int w = 1; w < 4; w++) {
                float ov = cv[s * 4 + w]; int ok = ck[s * 4 + w];
                if (ov > Bv || (ov == Bv && ok < Bk)) { Bv = ov; Bk = ok; }
            }
            int k = Bk;
            float2 Z1 = sY[k + (k >> 4)];
            int k2 = 4096 - k;
            float2 Z2 = sY[k2 + (k2 >> 4)];
            float Xr, Xi;
            if (s == 0) { Xr = 0.5f * (Z1.x + Z2.x); Xi = 0.5f * (Z1.y - Z2.y); }
            else        { Xr = 0.5f * (Z1.y + Z2.y); Xi = 0.5f * (Z2.x - Z1.x); }
            int sig = b * 256 + d0 + s;
            d_pk [sig * TOPK + r] = k;
            d_pre[sig * TOPK + r] = Xr * (4.0f / 4096.0f);
            d_pim[sig * TOPK + r] = Xi * (4.0f / 4096.0f);
            kb[s] = k;                  // broadcast winner
        }
        __syncthreads();
        if (r + 1 < TOPK) {
            int rel = kb[s] - 1 - lid;
            if (rel >= 0 && rel < 2048 && (rel & 127) == 0) {
                // this lane owned the winner: invalidate + rescan its 16
                int slot = rel >> 7;
                #pragma unroll
                for (int i = 0; i < 16; i++)
                    if (i == slot) mv[i] = -1.0f;
                bv = -2.0f; bk = 1 << 30;
                #pragma unroll
                for (int i = 0; i < 16; i++)
                    if (mv[i] > bv) { bv = mv[i]; bk = 1 + lid + 128 * i; }
            }
            __syncthreads();
        }
    }
}

// ---------------------------------------------------------------------------
// K2: reconstruction via Chebyshev 3-term recurrence (step = 8 samples)
//     p_n = 2*cos(8w)*p_{n-1} - p_{n-2}, exact-table seeds.
// block = (32 d-lanes, 8 t-phases); thread strides t by 8, 64 outputs.
// ---------------------------------------------------------------------------
__global__ void __launch_bounds__(256) k_recon(float* __restrict__ out) {
    int tx = threadIdx.x, ty = threadIdx.y;
    int d   = blockIdx.x * 32 + tx;
    int b   = blockIdx.y;
    int t0  = blockIdx.z * 512 + ty;
    int sig = b * 256 + d;

    float p0[TOPK], p1[TOPK], c2[TOPK];
    #pragma unroll
    for (int j = 0; j < TOPK; j++) {
        int   k  = d_pk [sig * TOPK + j];
        float cr = d_pre[sig * TOPK + j];
        float ci = d_pim[sig * TOPK + j];
        float2 w0 = d_tw[(k * t0) & 4095];        // (cos, -sin) of w*t0
        p0[j] = cr * w0.x + ci * w0.y;            // Re(C * e^{i w t0})
        float2 w1 = d_tw[(k * (t0 + 8)) & 4095];
        p1[j] = cr * w1.x + ci * w1.y;
        c2[j] = 2.0f * d_tw[(8 * k) & 4095].x;    // 2*cos(8w)
    }

    float* po = out + ((size_t)b * 4096 + t0) * 256 + d;
    {
        float a0 = ((p0[0] + p0[1]) + (p0[2] + p0[3])) + ((p0[4] + p0[5]) + p0[6]);
        float a1 = ((p1[0] + p1[1]) + (p1[2] + p1[3])) + ((p1[4] + p1[5]) + p1[6]);
        po[0]    = a0;
        po[2048] = a1;    // 8 * 256
    }

    #pragma unroll
    for (int n = 2; n < 64; n += 2) {
        #pragma unroll
        for (int j = 0; j < TOPK; j++) p0[j] = c2[j] * p1[j] - p0[j];
        po[(size_t)n * 2048] =
            ((p0[0] + p0[1]) + (p0[2] + p0[3])) + ((p0[4] + p0[5]) + p0[6]);
        #pragma unroll
        for (int j = 0; j < TOPK; j++) p1[j] = c2[j] * p0[j] - p1[j];
        po[(size_t)(n + 1) * 2048] =
            ((p1[0] + p1[1]) + (p1[2] + p1[3])) + ((p1[4] + p1[5]) + p1[6]);
    }
}

// ---------------------------------------------------------------------------
extern "C" void kernel_launch(void* const* d_in, const int* in_sizes, int n_in,
                              void* d_out, int out_size) {
    (void)in_sizes; (void)n_in; (void)out_size;
    const float* x = (const float*)d_in[0];
    float* out = (float*)d_out;

    cudaFuncSetAttribute(k_fft, cudaFuncAttributeMaxDynamicSharedMemorySize, 34944);

    k_twiddle<<<16, 256>>>();

    dim3 gt(128, 8, 16), bt(32, 8);
    k_transpose<<<gt, bt>>>(x);

    k_fft<<<2048, 256, 34944>>>();

    dim3 gr(8, 16, 8), br(32, 8);
    k_recon<<<gr, br>>>(out);
}

// round 6
// speedup vs baseline: 3.1206x; 1.0521x over previous
#include <cuda_runtime.h>
#include <math.h>
#include <stdint.h>

#define T_LEN 4096
#define NSIG  4096          // 16 * 256 signals
#define TOPK  7

// -------- scratch (module-scope device memory; no runtime allocation) -------
__device__ float2 d_tw[T_LEN];                  // e^{-2*pi*i*j/4096}
__device__ int    d_pk [NSIG * TOPK];           // selected frequency index k
__device__ float  d_pre[NSIG * TOPK];           // coefficient real = 4*Re(X)/T
__device__ float  d_pim[NSIG * TOPK];           // coefficient imag = 4*Im(X)/T

// W16^e = (cos(pi*e/8), -sin(pi*e/8)), e = 0..9
__constant__ float2 W16C[10] = {
    { 1.0f, 0.0f},
    { 0.92387953251128674f, -0.38268343236508978f},
    { 0.70710678118654752f, -0.70710678118654752f},
    { 0.38268343236508978f, -0.92387953251128674f},
    { 0.0f, -1.0f},
    { 0.0f,  0.0f},   // unused
    {-0.70710678118654752f, -0.70710678118654752f},
    { 0.0f,  0.0f},   // unused
    { 0.0f,  0.0f},   // unused
    {-0.92387953251128674f,  0.38268343236508978f},
};

// ---------------------------------------------------------------------------
// K0: twiddle table in double precision (exact-ish regardless of fast-math)
// ---------------------------------------------------------------------------
__global__ void k_twiddle() {
    int j = blockIdx.x * blockDim.x + threadIdx.x;
    if (j < T_LEN) {
        double a = -2.0 * 3.14159265358979323846 * (double)j / 4096.0;
        d_tw[j] = make_float2((float)cos(a), (float)sin(a));
    }
}

// ---------------------------------------------------------------------------
// complex helpers
// ---------------------------------------------------------------------------
__device__ __forceinline__ float2 cmul(float2 a, float2 b) {
    return make_float2(a.x * b.x - a.y * b.y, a.x * b.y + a.y * b.x);
}
__device__ __forceinline__ float2 cadd(float2 a, float2 b) { return make_float2(a.x + b.x, a.y + b.y); }
__device__ __forceinline__ float2 csub(float2 a, float2 b) { return make_float2(a.x - b.x, a.y - b.y); }
__device__ __forceinline__ float2 mnegi(float2 a) { return make_float2(a.y, -a.x); }  // -i * a

// In-place 16-point DFT: two radix-4 passes, NO temp array.
// After the call, Y[j] lives at slot YSLOT(j) = 4*(j&3) + (j>>2).
#define YSLOT(j) (4 * ((j) & 3) + ((j) >> 2))
__device__ __forceinline__ void dft16_ip(float2 v[16]) {
    #pragma unroll
    for (int m = 0; m < 4; m++) {
        float2 a0 = v[m], a1 = v[m + 4], a2 = v[m + 8], a3 = v[m + 12];
        float2 s02 = cadd(a0, a2), d02 = csub(a0, a2);
        float2 s13 = cadd(a1, a3), d13 = csub(a1, a3);
        float2 id  = mnegi(d13);
        v[m]      = cadd(s02, s13);
        v[m + 4]  = cadd(d02, id);
        v[m + 8]  = csub(s02, s13);
        v[m + 12] = csub(d02, id);
    }
    #pragma unroll
    for (int j1 = 1; j1 < 4; j1++)
        #pragma unroll
        for (int m = 1; m < 4; m++)
            v[m + 4 * j1] = cmul(v[m + 4 * j1], W16C[m * j1]);
    #pragma unroll
    for (int g = 0; g < 4; g++) {
        float2 a0 = v[4*g], a1 = v[4*g + 1], a2 = v[4*g + 2], a3 = v[4*g + 3];
        float2 s02 = cadd(a0, a2), d02 = csub(a0, a2);
        float2 s13 = cadd(a1, a3), d13 = csub(a1, a3);
        float2 id  = mnegi(d13);
        v[4*g]     = cadd(s02, s13);
        v[4*g + 1] = cadd(d02, id);
        v[4*g + 2] = csub(s02, s13);
        v[4*g + 3] = csub(d02, id);
    }
}

// ---------------------------------------------------------------------------
// K1: 4096 = 16^3 self-sorting FFT (2 real signals packed), then top-7 on
// register-resident squared magnitudes. Stage 1 reads x DIRECTLY in its
// native (b,t,d) layout: the packed pair IS the adjacent d-channel pair,
// so one float2 load gives (sig0[t], sig1[t]). No transpose kernel.
// Smem: one padded buffer (16*272 float2 = 34816 B) + 72 B scratch.
// ---------------------------------------------------------------------------
__global__ void __launch_bounds__(256, 3) k_fft(const float* __restrict__ x) {
    extern __shared__ char smraw[];
    float2* sY = (float2*)smraw;                 // 4352 float2 (34816 B)
    float*  cv = (float*)(smraw + 34816);        // 8 floats
    int*    ck = (int*)  (smraw + 34816 + 32);   // 8 ints
    int*    kb = (int*)  (smraw + 34816 + 64);   // 2 ints (winner broadcast)

    int tid = threadIdx.x;
    int b   = blockIdx.x >> 7;
    int d0  = (blockIdx.x & 127) << 1;

    float2 v[16];

    // ---- stage 1: a = tid; y1[a,j] = DFT16_r(x[a+256r]) * W4096^{a*j} ----
    {
        int a = tid;
        // float2 element index of x[b, t=a, d0]: (b*4096 + a)*128 + d0/2
        const float2* xp = (const float2*)x
                         + ((size_t)b * 4096 + a) * 128 + (d0 >> 1);
        #pragma unroll
        for (int r = 0; r < 16; r++)
            v[r] = xp[(size_t)r * 32768];        // t += 256  ->  +256*128
        dft16_ip(v);
        int c = a >> 4, bb = a & 15;
        float2 w = d_tw[a];
        float2 p = w;
        sY[0 * 272 + c * 17 + bb] = v[YSLOT(0)];
        #pragma unroll
        for (int j = 1; j < 16; j++) {
            sY[j * 272 + c * 17 + bb] = cmul(v[YSLOT(j)], p);
            p = cmul(p, w);
        }
    }
    __syncthreads();

    // ---- stage 2 (in place; each thread owns its address set) ----
    {
        int j = tid >> 4, bb = tid & 15;
        int base = j * 272 + bb;
        #pragma unroll
        for (int c = 0; c < 16; c++) v[c] = sY[base + c * 17];
        dft16_ip(v);
        float2 w = d_tw[16 * bb];
        float2 p = w;
        sY[base] = v[YSLOT(0)];
        #pragma unroll
        for (int i = 1; i < 16; i++) {
            sY[base + i * 17] = cmul(v[YSLOT(i)], p);
            p = cmul(p, w);
        }
    }
    __syncthreads();

    // ---- stage 3: read own set into regs, sync, scatter spectrum ----
    {
        int j = tid >> 4, i = tid & 15;
        #pragma unroll
        for (int bb = 0; bb < 16; bb++) v[bb] = sY[j * 272 + i * 17 + bb];
        dft16_ip(v);
        __syncthreads();
        // X[k], k = j+16i+256l, stored at k + (k>>4) = j + 17i + 272l
        #pragma unroll
        for (int l = 0; l < 16; l++)
            sY[j + 17 * i + 272 * l] = v[YSLOT(l)];
    }
    __syncthreads();

    // ---- top-7 on squared magnitudes, register-resident ----
    // warps 0-3 -> signal 0, warps 4-7 -> signal 1; lane lid owns
    // k = 1 + lid + 128*i for i = 0..15 (k = 2048 slot invalidated).
    int s    = tid >> 7;
    int lid  = tid & 127;
    int wid  = tid >> 5;
    int lane = tid & 31;

    float mv[16];
    #pragma unroll
    for (int i = 0; i < 16; i++) {
        int k = 1 + lid + 128 * i;
        float m2 = -1.0f;
        if (k < 2048) {
            float2 Z1 = sY[k + (k >> 4)];
            int k2 = 4096 - k;
            float2 Z2 = sY[k2 + (k2 >> 4)];
            float xr, xi;
            if (s == 0) { xr = Z1.x + Z2.x; xi = Z1.y - Z2.y; }
            else        { xr = Z1.y + Z2.y; xi = Z2.x - Z1.x; }
            m2 = xr * xr + xi * xi;     // 4*|X|^2 (monotone in |X|)
        }
        mv[i] = m2;
    }

    // persistent per-lane best (strict > keeps lowest k within a lane)
    float bv = -2.0f; int bk = 1 << 30;
    #pragma unroll
    for (int i = 0; i < 16; i++)
        if (mv[i] > bv) { bv = mv[i]; bk = 1 + lid + 128 * i; }

    for (int r = 0; r < TOPK; r++) {
        // warp-level reduction (non-destructive copies)
        float rv = bv; int rk = bk;
        #pragma unroll
        for (int off = 16; off; off >>= 1) {
            float ov = __shfl_down_sync(0xffffffffu, rv, off);
            int   ok = __shfl_down_sync(0xffffffffu, rk, off);
            if (ov > rv || (ov == rv && ok < rk)) { rv = ov; rk = ok; }
        }
        if (lane == 0) { cv[wid] = rv; ck[wid] = rk; }
        __syncthreads();
        if (lid == 0) {
            float Bv = cv[s * 4]; int Bk = ck[s * 4];
            #pragma unroll
            for (int w = 1; w < 4; w++) {
                float ov = cv[s * 4 + w]; int ok = ck[s * 4 + w];
                if (ov > Bv || (ov == Bv && ok < Bk)) { Bv = ov; Bk = ok; }
            }
            int k = Bk;
            float2 Z1 = sY[k + (k >> 4)];
            int k2 = 4096 - k;
            float2 Z2 = sY[k2 + (k2 >> 4)];
            float Xr, Xi;
            if (s == 0) { Xr = 0.5f * (Z1.x + Z2.x); Xi = 0.5f * (Z1.y - Z2.y); }
            else        { Xr = 0.5f * (Z1.y + Z2.y); Xi = 0.5f * (Z2.x - Z1.x); }
            int sig = b * 256 + d0 + s;
            d_pk [sig * TOPK + r] = k;
            d_pre[sig * TOPK + r] = Xr * (4.0f / 4096.0f);
            d_pim[sig * TOPK + r] = Xi * (4.0f / 4096.0f);
            kb[s] = k;                  // broadcast winner
        }
        __syncthreads();
        if (r + 1 < TOPK) {
            int rel = kb[s] - 1 - lid;
            if (rel >= 0 && rel < 2048 && (rel & 127) == 0) {
                // this lane owned the winner: invalidate + rescan its 16
                int slot = rel >> 7;
                #pragma unroll
                for (int i = 0; i < 16; i++)
                    if (i == slot) mv[i] = -1.0f;
                bv = -2.0f; bk = 1 << 30;
                #pragma unroll
                for (int i = 0; i < 16; i++)
                    if (mv[i] > bv) { bv = mv[i]; bk = 1 + lid + 128 * i; }
            }
            __syncthreads();
        }
    }
}

// ---------------------------------------------------------------------------
// K2: reconstruction via Chebyshev 3-term recurrence (step = 8 samples)
//     p_n = 2*cos(8w)*p_{n-1} - p_{n-2}, exact-table seeds.
// block = (32 d-lanes, 8 t-phases); thread strides t by 8, 64 outputs.
// ---------------------------------------------------------------------------
__global__ void __launch_bounds__(256) k_recon(float* __restrict__ out) {
    int tx = threadIdx.x, ty = threadIdx.y;
    int d   = blockIdx.x * 32 + tx;
    int b   = blockIdx.y;
    int t0  = blockIdx.z * 512 + ty;
    int sig = b * 256 + d;

    float p0[TOPK], p1[TOPK], c2[TOPK];
    #pragma unroll
    for (int j = 0; j < TOPK; j++) {
        int   k  = d_pk [sig * TOPK + j];
        float cr = d_pre[sig * TOPK + j];
        float ci = d_pim[sig * TOPK + j];
        float2 w0 = d_tw[(k * t0) & 4095];        // (cos, -sin) of w*t0
        p0[j] = cr * w0.x + ci * w0.y;            // Re(C * e^{i w t0})
        float2 w1 = d_tw[(k * (t0 + 8)) & 4095];
        p1[j] = cr * w1.x + ci * w1.y;
        c2[j] = 2.0f * d_tw[(8 * k) & 4095].x;    // 2*cos(8w)
    }

    float* po = out + ((size_t)b * 4096 + t0) * 256 + d;
    {
        float a0 = ((p0[0] + p0[1]) + (p0[2] + p0[3])) + ((p0[4] + p0[5]) + p0[6]);
        float a1 = ((p1[0] + p1[1]) + (p1[2] + p1[3])) + ((p1[4] + p1[5]) + p1[6]);
        po[0]    = a0;
        po[2048] = a1;    // 8 * 256
    }

    #pragma unroll
    for (int n = 2; n < 64; n += 2) {
        #pragma unroll
        for (int j = 0; j < TOPK; j++) p0[j] = c2[j] * p1[j] - p0[j];
        po[(size_t)n * 2048] =
            ((p0[0] + p0[1]) + (p0[2] + p0[3])) + ((p0[4] + p0[5]) + p0[6]);
        #pragma unroll
        for (int j = 0; j < TOPK; j++) p1[j] = c2[j] * p0[j] - p1[j];
        po[(size_t)(n + 1) * 2048] =
            ((p1[0] + p1[1]) + (p1[2] + p1[3])) + ((p1[4] + p1[5]) + p1[6]);
    }
}

// ---------------------------------------------------------------------------
extern "C" void kernel_launch(void* const* d_in, const int* in_sizes, int n_in,
                              void* d_out, int out_size) {
    (void)in_sizes; (void)n_in; (void)out_size;
    const float* x = (const float*)d_in[0];
    float* out = (float*)d_out;

    cudaFuncSetAttribute(k_fft, cudaFuncAttributeMaxDynamicSharedMemorySize, 34944);

    k_twiddle<<<16, 256>>>();

    k_fft<<<2048, 256, 34944>>>(x);

    dim3 gr(8, 16, 8), br(32, 8);
    k_recon<<<gr, br>>>(out);
}

// round 7
// speedup vs baseline: 3.2771x; 1.0501x over previous
#include <cuda_runtime.h>
#include <math.h>
#include <stdint.h>

#define T_LEN 4096
#define NSIG  4096          // 16 * 256 signals
#define TOPK  7

// -------- scratch (module-scope device memory; no runtime allocation) -------
__device__ float2 d_tw[T_LEN];                  // e^{-2*pi*i*j/4096}
__device__ int    d_pk [NSIG * TOPK];           // selected frequency index k
__device__ float  d_pre[NSIG * TOPK];           // coefficient real = 4*Re(X)/T
__device__ float  d_pim[NSIG * TOPK];           // coefficient imag = 4*Im(X)/T

// W16^e = (cos(pi*e/8), -sin(pi*e/8)), e = 0..9
__constant__ float2 W16C[10] = {
    { 1.0f, 0.0f},
    { 0.92387953251128674f, -0.38268343236508978f},
    { 0.70710678118654752f, -0.70710678118654752f},
    { 0.38268343236508978f, -0.92387953251128674f},
    { 0.0f, -1.0f},
    { 0.0f,  0.0f},   // unused
    {-0.70710678118654752f, -0.70710678118654752f},
    { 0.0f,  0.0f},   // unused
    { 0.0f,  0.0f},   // unused
    {-0.92387953251128674f,  0.38268343236508978f},
};

// ---------------------------------------------------------------------------
// K0: twiddle table via sincospif (1-2 ulp; arg -j/2048 exact in fp32).
// NOT affected by --use_fast_math (no fast-path mapping for sincospif).
// ---------------------------------------------------------------------------
__global__ void k_twiddle() {
    int j = blockIdx.x * blockDim.x + threadIdx.x;
    if (j < T_LEN) {
        float sp, cp;
        sincospif(-(float)j * (1.0f / 2048.0f), &sp, &cp);
        d_tw[j] = make_float2(cp, sp);
    }
}

// ---------------------------------------------------------------------------
// complex helpers
// ---------------------------------------------------------------------------
__device__ __forceinline__ float2 cmul(float2 a, float2 b) {
    return make_float2(a.x * b.x - a.y * b.y, a.x * b.y + a.y * b.x);
}
__device__ __forceinline__ float2 cadd(float2 a, float2 b) { return make_float2(a.x + b.x, a.y + b.y); }
__device__ __forceinline__ float2 csub(float2 a, float2 b) { return make_float2(a.x - b.x, a.y - b.y); }
__device__ __forceinline__ float2 mnegi(float2 a) { return make_float2(a.y, -a.x); }  // -i * a

// In-place 16-point DFT: two radix-4 passes, NO temp array.
// After the call, Y[j] lives at slot YSLOT(j) = 4*(j&3) + (j>>2).
#define YSLOT(j) (4 * ((j) & 3) + ((j) >> 2))
__device__ __forceinline__ void dft16_ip(float2 v[16]) {
    #pragma unroll
    for (int m = 0; m < 4; m++) {
        float2 a0 = v[m], a1 = v[m + 4], a2 = v[m + 8], a3 = v[m + 12];
        float2 s02 = cadd(a0, a2), d02 = csub(a0, a2);
        float2 s13 = cadd(a1, a3), d13 = csub(a1, a3);
        float2 id  = mnegi(d13);
        v[m]      = cadd(s02, s13);
        v[m + 4]  = cadd(d02, id);
        v[m + 8]  = csub(s02, s13);
        v[m + 12] = csub(d02, id);
    }
    #pragma unroll
    for (int j1 = 1; j1 < 4; j1++)
        #pragma unroll
        for (int m = 1; m < 4; m++)
            v[m + 4 * j1] = cmul(v[m + 4 * j1], W16C[m * j1]);
    #pragma unroll
    for (int g = 0; g < 4; g++) {
        float2 a0 = v[4*g], a1 = v[4*g + 1], a2 = v[4*g + 2], a3 = v[4*g + 3];
        float2 s02 = cadd(a0, a2), d02 = csub(a0, a2);
        float2 s13 = cadd(a1, a3), d13 = csub(a1, a3);
        float2 id  = mnegi(d13);
        v[4*g]     = cadd(s02, s13);
        v[4*g + 1] = cadd(d02, id);
        v[4*g + 2] = csub(s02, s13);
        v[4*g + 3] = csub(d02, id);
    }
}

// ---------------------------------------------------------------------------
// K1: 4096 = 16^3 self-sorting FFT (2 real signals packed), then top-7 on
// register-resident squared magnitudes. Stage 1 reads x DIRECTLY in its
// native (b,t,d) layout (adjacent d-pair = the packed complex value).
// 4 blocks/SM (regs capped at 64) so one block's load burst overlaps
// another block's FMA phase.
// ---------------------------------------------------------------------------
__global__ void __launch_bounds__(256, 4) k_fft(const float* __restrict__ x) {
    extern __shared__ char smraw[];
    float2* sY = (float2*)smraw;                 // 4352 float2 (34816 B)
    float*  cv = (float*)(smraw + 34816);        // 8 floats
    int*    ck = (int*)  (smraw + 34816 + 32);   // 8 ints
    int*    kb = (int*)  (smraw + 34816 + 64);   // 2 ints (winner broadcast)

    int tid = threadIdx.x;
    int b   = blockIdx.x >> 7;
    int d0  = (blockIdx.x & 127) << 1;

    float2 v[16];

    // ---- stage 1: a = tid; y1[a,j] = DFT16_r(x[a+256r]) * W4096^{a*j} ----
    {
        int a = tid;
        // float2 element index of x[b, t=a, d0]: (b*4096 + a)*128 + d0/2
        const float2* xp = (const float2*)x
                         + ((size_t)b * 4096 + a) * 128 + (d0 >> 1);
        #pragma unroll
        for (int r = 0; r < 16; r++)
            v[r] = xp[(size_t)r * 32768];        // t += 256  ->  +256*128
        dft16_ip(v);
        int c = a >> 4, bb = a & 15;
        float2 w = d_tw[a];
        float2 p = w;
        sY[0 * 272 + c * 17 + bb] = v[YSLOT(0)];
        #pragma unroll
        for (int j = 1; j < 16; j++) {
            sY[j * 272 + c * 17 + bb] = cmul(v[YSLOT(j)], p);
            p = cmul(p, w);
        }
    }
    __syncthreads();

    // ---- stage 2 (in place; each thread owns its address set) ----
    {
        int j = tid >> 4, bb = tid & 15;
        int base = j * 272 + bb;
        #pragma unroll
        for (int c = 0; c < 16; c++) v[c] = sY[base + c * 17];
        dft16_ip(v);
        float2 w = d_tw[16 * bb];
        float2 p = w;
        sY[base] = v[YSLOT(0)];
        #pragma unroll
        for (int i = 1; i < 16; i++) {
            sY[base + i * 17] = cmul(v[YSLOT(i)], p);
            p = cmul(p, w);
        }
    }
    __syncthreads();

    // ---- stage 3: read own set into regs, sync, scatter spectrum ----
    {
        int j = tid >> 4, i = tid & 15;
        #pragma unroll
        for (int bb = 0; bb < 16; bb++) v[bb] = sY[j * 272 + i * 17 + bb];
        dft16_ip(v);
        __syncthreads();
        // X[k], k = j+16i+256l, stored at k + (k>>4) = j + 17i + 272l
        #pragma unroll
        for (int l = 0; l < 16; l++)
            sY[j + 17 * i + 272 * l] = v[YSLOT(l)];
    }
    __syncthreads();

    // ---- top-7 on squared magnitudes, register-resident ----
    // warps 0-3 -> signal 0, warps 4-7 -> signal 1; lane lid owns
    // k = 1 + lid + 128*i for i = 0..15 (k = 2048 slot invalidated).
    int s    = tid >> 7;
    int lid  = tid & 127;
    int wid  = tid >> 5;
    int lane = tid & 31;

    float mv[16];
    #pragma unroll
    for (int i = 0; i < 16; i++) {
        int k = 1 + lid + 128 * i;
        float m2 = -1.0f;
        if (k < 2048) {
            float2 Z1 = sY[k + (k >> 4)];
            int k2 = 4096 - k;
            float2 Z2 = sY[k2 + (k2 >> 4)];
            float xr, xi;
            if (s == 0) { xr = Z1.x + Z2.x; xi = Z1.y - Z2.y; }
            else        { xr = Z1.y + Z2.y; xi = Z2.x - Z1.x; }
            m2 = xr * xr + xi * xi;     // 4*|X|^2 (monotone in |X|)
        }
        mv[i] = m2;
    }

    // persistent per-lane best (strict > keeps lowest k within a lane)
    float bv = -2.0f; int bk = 1 << 30;
    #pragma unroll
    for (int i = 0; i < 16; i++)
        if (mv[i] > bv) { bv = mv[i]; bk = 1 + lid + 128 * i; }

    for (int r = 0; r < TOPK; r++) {
        // warp-level reduction (non-destructive copies)
        float rv = bv; int rk = bk;
        #pragma unroll
        for (int off = 16; off; off >>= 1) {
            float ov = __shfl_down_sync(0xffffffffu, rv, off);
            int   ok = __shfl_down_sync(0xffffffffu, rk, off);
            if (ov > rv || (ov == rv && ok < rk)) { rv = ov; rk = ok; }
        }
        if (lane == 0) { cv[wid] = rv; ck[wid] = rk; }
        __syncthreads();
        if (lid == 0) {
            float Bv = cv[s * 4]; int Bk = ck[s * 4];
            #pragma unroll
            for (int w = 1; w < 4; w++) {
                float ov = cv[s * 4 + w]; int ok = ck[s * 4 + w];
                if (ov > Bv || (ov == Bv && ok < Bk)) { Bv = ov; Bk = ok; }
            }
            int k = Bk;
            float2 Z1 = sY[k + (k >> 4)];
            int k2 = 4096 - k;
            float2 Z2 = sY[k2 + (k2 >> 4)];
            float Xr, Xi;
            if (s == 0) { Xr = 0.5f * (Z1.x + Z2.x); Xi = 0.5f * (Z1.y - Z2.y); }
            else        { Xr = 0.5f * (Z1.y + Z2.y); Xi = 0.5f * (Z2.x - Z1.x); }
            int sig = b * 256 + d0 + s;
            d_pk [sig * TOPK + r] = k;
            d_pre[sig * TOPK + r] = Xr * (4.0f / 4096.0f);
            d_pim[sig * TOPK + r] = Xi * (4.0f / 4096.0f);
            kb[s] = k;                  // broadcast winner
        }
        __syncthreads();
        if (r + 1 < TOPK) {
            int rel = kb[s] - 1 - lid;
            if (rel >= 0 && rel < 2048 && (rel & 127) == 0) {
                // this lane owned the winner: invalidate + rescan its 16
                int slot = rel >> 7;
                #pragma unroll
                for (int i = 0; i < 16; i++)
                    if (i == slot) mv[i] = -1.0f;
                bv = -2.0f; bk = 1 << 30;
                #pragma unroll
                for (int i = 0; i < 16; i++)
                    if (mv[i] > bv) { bv = mv[i]; bk = 1 + lid + 128 * i; }
            }
            __syncthreads();
        }
    }
}

// ---------------------------------------------------------------------------
// K2: reconstruction via Chebyshev 3-term recurrence (step = 8 samples)
//     p_n = 2*cos(8w)*p_{n-1} - p_{n-2}, exact-table seeds.
// block = (32 d-lanes, 8 t-phases); thread strides t by 8, 128 outputs.
// (R4 configuration: z=4, unroll 4, ~32 regs — measured best.)
// ---------------------------------------------------------------------------
__global__ void __launch_bounds__(256) k_recon(float* __restrict__ out) {
    int tx = threadIdx.x, ty = threadIdx.y;
    int d   = blockIdx.x * 32 + tx;
    int b   = blockIdx.y;
    int t0  = blockIdx.z * 1024 + ty;
    int sig = b * 256 + d;

    float p0[TOPK], p1[TOPK], c2[TOPK];
    #pragma unroll
    for (int j = 0; j < TOPK; j++) {
        int   k  = d_pk [sig * TOPK + j];
        float cr = d_pre[sig * TOPK + j];
        float ci = d_pim[sig * TOPK + j];
        float2 w0 = d_tw[(k * t0) & 4095];        // (cos, -sin) of w*t0
        p0[j] = cr * w0.x + ci * w0.y;            // Re(C * e^{i w t0})
        float2 w1 = d_tw[(k * (t0 + 8)) & 4095];
        p1[j] = cr * w1.x + ci * w1.y;
        c2[j] = 2.0f * d_tw[(8 * k) & 4095].x;    // 2*cos(8w)
    }

    float* po = out + ((size_t)b * 4096 + t0) * 256 + d;
    {
        float a0 = 0.0f, a1 = 0.0f;
        #pragma unroll
        for (int j = 0; j < TOPK; j++) { a0 += p0[j]; a1 += p1[j]; }
        po[0]    = a0;
        po[2048] = a1;    // 8 * 256
    }

    #pragma unroll 4
    for (int n = 2; n < 128; n += 2) {
        float s0 = 0.0f, s1 = 0.0f;
        #pragma unroll
        for (int j = 0; j < TOPK; j++) {
            p0[j] = c2[j] * p1[j] - p0[j];
            s0 += p0[j];
        }
        po[(size_t)n * 2048] = s0;
        #pragma unroll
        for (int j = 0; j < TOPK; j++) {
            p1[j] = c2[j] * p0[j] - p1[j];
            s1 += p1[j];
        }
        po[(size_t)(n + 1) * 2048] = s1;
    }
}

// ---------------------------------------------------------------------------
extern "C" void kernel_launch(void* const* d_in, const int* in_sizes, int n_in,
                              void* d_out, int out_size) {
    (void)in_sizes; (void)n_in; (void)out_size;
    const float* x = (const float*)d_in[0];
    float* out = (float*)d_out;

    cudaFuncSetAttribute(k_fft, cudaFuncAttributeMaxDynamicSharedMemorySize, 34944);

    k_twiddle<<<32, 128>>>();

    k_fft<<<2048, 256, 34944>>>(x);

    dim3 gr(8, 16, 4), br(32, 8);
    k_recon<<<gr, br>>>(out);
}